// round 12
// baseline (speedup 1.0000x reference)
#include <cuda_runtime.h>
#include <cuda_bf16.h>
#include <cuda_fp16.h>
#include <cuda_fp8.h>
#include <cstdint>

// Problem constants (fixed shape: path_fea [131072, 64, 1, 1, 2] fp32)
#define GNUM 8192        // groups = B / 16
#define PNUM 16          // samples per group
#define DNUM 128         // feature dim
#define NTILE 64         // GNUM / 128
#define NTILES_TRI 2080  // 64*65/2 triangular 128x128 tiles
#define GRID_B 592       // persistent CTAs (148 SMs * 4)
#define TROW 144         // smem tile row stride in bytes (128 fp8 + 16 pad)
#define TILEB (128 * TROW)

// -------- device scratch (no allocs allowed) --------
__device__ uint8_t g_centerF8[GNUM * DNUM];   // e4m3 centers (k-major, 128B/row)
__device__ float g_sq[GNUM];                  // fp32 ||c||^2
__device__ float g_intra_part[GNUM];
__device__ float g_inter_part[GRID_B];
__device__ unsigned int g_sqmin_bits = 0x7F7FFFFFu;  // FLT_MAX bits; self-resetting
__device__ unsigned int g_done = 0;                  // self-resetting

// ===================== helpers =====================
__device__ __forceinline__ uint32_t smem_u32(const void* p) {
    uint32_t a;
    asm("{ .reg .u64 t; cvta.to.shared.u64 t, %1; cvt.u32.u64 %0, t; }"
        : "=r"(a) : "l"(p));
    return a;
}
__device__ __forceinline__ void cp16(uint32_t dst, const void* src) {
    asm volatile("cp.async.cg.shared.global [%0], [%1], 16;"
                 :: "r"(dst), "l"(src) : "memory");
}
__device__ __forceinline__ void cp_commit() {
    asm volatile("cp.async.commit_group;" ::: "memory");
}
__device__ __forceinline__ void cp_wait0() {
    asm volatile("cp.async.wait_group 0;" ::: "memory");
}
__device__ __forceinline__ void ldm_x4_raw(uint32_t (&r)[4], uint32_t addr) {
    asm volatile("ldmatrix.sync.aligned.m8n8.x4.shared.b16 {%0,%1,%2,%3}, [%4];"
        : "=r"(r[0]), "=r"(r[1]), "=r"(r[2]), "=r"(r[3]) : "r"(addr));
}
// FP8 e4m3 MMA with f16 accumulators
__device__ __forceinline__ void mma_fp8_h(uint32_t (&d)[2], const uint32_t (&a)[4],
                                          uint32_t b0, uint32_t b1) {
    asm volatile(
        "mma.sync.aligned.m16n8k32.row.col.f16.e4m3.e4m3.f16 "
        "{%0,%1}, {%2,%3,%4,%5}, {%6,%7}, {%0,%1};"
        : "+r"(d[0]), "+r"(d[1])
        : "r"(a[0]), "r"(a[1]), "r"(a[2]), "r"(a[3]), "r"(b0), "r"(b1));
}

// ============================================================
// Kernel A: per-group center + ||c||^2 + intra hinge (memory-bound,
// wide grid to saturate HBM) + global-min(||c||^2) via atomicMin
// ============================================================
__global__ void __launch_bounds__(512) center_intra_kernel(const float* __restrict__ fea) {
    __shared__ float sf[PNUM * DNUM];
    __shared__ float sc[DNUM];
    __shared__ float s_red[4];
    __shared__ float s_h[PNUM];

    const int g = blockIdx.x;
    const int tid = threadIdx.x;

    const float4* base4 = (const float4*)(fea + (size_t)g * (PNUM * DNUM));
    ((float4*)sf)[tid] = base4[tid];
    __syncthreads();

    float c = 0.0f;
    if (tid < DNUM) {
        #pragma unroll
        for (int s = 0; s < PNUM; s++) c += sf[s * DNUM + tid];
        c *= (1.0f / PNUM);
        sc[tid] = c;
        g_centerF8[(size_t)g * DNUM + tid] =
            (uint8_t)__nv_cvt_float_to_fp8(c, __NV_SATFINITE, __NV_E4M3);
    }
    float cs = (tid < DNUM) ? c * c : 0.0f;
    #pragma unroll
    for (int o = 16; o > 0; o >>= 1) cs += __shfl_down_sync(0xffffffffu, cs, o);
    if (tid < DNUM && (tid & 31) == 0) s_red[tid >> 5] = cs;
    __syncthreads();
    if (tid == 0) {
        float sq = s_red[0] + s_red[1] + s_red[2] + s_red[3];
        g_sq[g] = sq;
        atomicMin(&g_sqmin_bits, __float_as_uint(sq));  // sq >= 0: bit order = float order
    }

    const int w = tid >> 5, l = tid & 31;
    float acc = 0.0f;
    #pragma unroll
    for (int q = 0; q < 4; q++) {
        int dd = l + 32 * q;
        float df = sf[w * DNUM + dd] - sc[dd];
        acc += df * df;
    }
    #pragma unroll
    for (int o = 16; o > 0; o >>= 1) acc += __shfl_down_sync(0xffffffffu, acc, o);
    if (l == 0) {
        float d = fmaxf(sqrtf(acc) - 0.1f, 0.0f);
        s_h[w] = d * d;
    }
    __syncthreads();
    if (tid == 0) {
        float t = 0.0f;
        #pragma unroll
        for (int s = 0; s < PNUM; s++) t += s_h[s];
        g_intra_part[g] = t;
    }
}

// ============================================================
// Kernel B: persistent FP8 QMMA SYRK (128x128 tiles, f16 accum),
// A single-buffered + B double-buffered (3 x 18KB smem -> 4 CTAs/SM),
// max-screened hinge epilogue, fused finalize (last CTA).
// ============================================================
__global__ void __launch_bounds__(256, 4) gram_finalize_kernel(float* __restrict__ out) {
    extern __shared__ uint8_t sm[];
    uint8_t* bufA = sm;
    uint8_t* bufB[2] = { sm + TILEB, sm + 2 * TILEB };

    __shared__ float s_red[8];
    __shared__ unsigned s_last;

    const int tid = threadIdx.x;
    const int wid = tid >> 5, lane = tid & 31;

    const int t0 = (int)(((long long)blockIdx.x * NTILES_TRI) / GRID_B);
    const int t1 = (int)(((long long)(blockIdx.x + 1) * NTILES_TRI) / GRID_B);

    int ti = 0, rowoff = 0;
    while (t0 >= rowoff + (NTILE - ti)) { rowoff += NTILE - ti; ti++; }
    int tj = ti + (t0 - rowoff);

    const uint8_t* gcb = g_centerF8;
    auto load_tile = [&](uint8_t* dst, int g0) {
        #pragma unroll
        for (int i = 0; i < 4; i++) {
            int u = tid + 256 * i;
            int r = u >> 3, c16 = (u & 7) * 16;
            cp16(smem_u32(dst + r * TROW + c16),
                 gcb + (size_t)(g0 + r) * 128 + c16);
        }
    };

    // prologue loads
    load_tile(bufA, ti * 128);
    load_tile(bufB[0], tj * 128);
    cp_commit();

    const float screen = __uint_as_float(g_sqmin_bits) - 0.5f;

    const int wm = wid & 1;
    const int wn = wid >> 1;
    const int lrow = lane & 15;
    const int lcolB = ((lane >> 4) << 3) * 2;
    const int r_l = lane >> 2;
    const int c_l = 2 * (lane & 3);

    // precomputed per-warp smem base addresses (raw, loop-constant)
    const uint32_t baseA = smem_u32(bufA) + (64 * wm + lrow) * TROW + lcolB;
    const uint32_t baseB0 = smem_u32(bufB[0]) + (32 * wn + lrow) * TROW + lcolB;
    const uint32_t baseB1 = smem_u32(bufB[1]) + (32 * wn + lrow) * TROW + lcolB;

    int cur = 0;
    float lsum = 0.0f;

    for (int t = t0; t < t1; t++) {
        const int i0 = ti * 128, j0 = tj * 128;
        cp_wait0();
        __syncthreads();

        int nti = ti, ntj = tj + 1;
        if (ntj == NTILE) { nti = ti + 1; ntj = nti; }
        const bool havenext = (t + 1 < t1);
        const bool newrow = (nti != ti);

        // B prefetch always overlaps compute (other B buffer is free)
        if (havenext) {
            load_tile(bufB[cur ^ 1], ntj * 128);
            cp_commit();
        }

        // ---- compute 128x128 tile: 4 k-steps of k32 ----
        const uint32_t baseB = cur ? baseB1 : baseB0;
        uint32_t acc[4][4][2];
        #pragma unroll
        for (int mt = 0; mt < 4; mt++)
            #pragma unroll
            for (int nt = 0; nt < 4; nt++) { acc[mt][nt][0] = 0u; acc[mt][nt][1] = 0u; }

        #pragma unroll
        for (int ks = 0; ks < 4; ks++) {
            const int kb = ks * 32;
            uint32_t a[4][4];
            #pragma unroll
            for (int mt = 0; mt < 4; mt++)
                ldm_x4_raw(a[mt], baseA + mt * (16 * TROW) + kb);
            uint32_t b0r[4], b1r[4];
            ldm_x4_raw(b0r, baseB + kb);
            ldm_x4_raw(b1r, baseB + 16 * TROW + kb);

            #pragma unroll
            for (int mt = 0; mt < 4; mt++) {
                mma_fp8_h(acc[mt][0], a[mt], b0r[0], b0r[2]);
                mma_fp8_h(acc[mt][1], a[mt], b0r[1], b0r[3]);
                mma_fp8_h(acc[mt][2], a[mt], b1r[0], b1r[2]);
                mma_fp8_h(acc[mt][3], a[mt], b1r[1], b1r[3]);
            }
        }

        // ---- epilogue: packed-max screen, exact path only if needed ----
        const bool diag = (ti == tj);
        __half2 m2 = __float2half2_rn(-60000.0f);
        #pragma unroll
        for (int mt = 0; mt < 4; mt++)
            #pragma unroll
            for (int nt = 0; nt < 4; nt++) {
                m2 = __hmax2(m2, *(const __half2*)&acc[mt][nt][0]);
                m2 = __hmax2(m2, *(const __half2*)&acc[mt][nt][1]);
            }
        float maxg = fmaxf(__low2float(m2), __high2float(m2));

        if (diag || maxg > screen) {
            // exact (diagonal tiles / vanishingly rare screen failures)
            #pragma unroll 1
            for (int mt = 0; mt < 4; mt++) {
                const int li0 = 64 * wm + 16 * mt + r_l;
                const float qa0 = __ldg(&g_sq[i0 + li0]);
                const float qa1 = __ldg(&g_sq[i0 + li0 + 8]);
                #pragma unroll 1
                for (int nt = 0; nt < 4; nt++) {
                    const int lj0 = 32 * wn + 8 * nt + c_l;
                    const float qb0 = __ldg(&g_sq[j0 + lj0]);
                    const float qb1 = __ldg(&g_sq[j0 + lj0 + 1]);
                    float2 v0 = __half22float2(*(const __half2*)&acc[mt][nt][0]);
                    float2 v1 = __half22float2(*(const __half2*)&acc[mt][nt][1]);
                    const float gv[4]  = { v0.x, v0.y, v1.x, v1.y };
                    const float qav[4] = { qa0, qa0, qa1, qa1 };
                    const float qbv[4] = { qb0, qb1, qb0, qb1 };
                    const int liv[4] = { li0, li0, li0 + 8, li0 + 8 };
                    const int ljv[4] = { lj0, lj0 + 1, lj0, lj0 + 1 };
                    #pragma unroll
                    for (int e = 0; e < 4; e++) {
                        bool ok = !diag || (liv[e] < ljv[e]);
                        float d2 = qav[e] + qbv[e] - 2.0f * gv[e];
                        if (ok && d2 < 1.0f) {
                            float d = sqrtf(fmaxf(d2, 0.0f));
                            float h = 1.0f - d;
                            lsum += h * h;
                        }
                    }
                }
            }
        }

        // row transition: A buffer reload (compute already done; B prefetch untouched)
        if (havenext && newrow) {
            __syncthreads();            // everyone finished reading bufA
            load_tile(bufA, nti * 128);
            cp_commit();                // waited at next loop-top
        }

        cur ^= 1;
        ti = nti; tj = ntj;
    }

    // per-CTA inter reduction
    #pragma unroll
    for (int o = 16; o > 0; o >>= 1) lsum += __shfl_down_sync(0xffffffffu, lsum, o);
    __syncthreads();
    if (lane == 0) s_red[wid] = lsum;
    __syncthreads();
    if (tid == 0) {
        float tsum = 0.0f;
        #pragma unroll
        for (int w = 0; w < 8; w++) tsum += s_red[w];
        g_inter_part[blockIdx.x] = tsum;
    }

    // last-CTA-done finalize
    __threadfence();
    __syncthreads();
    if (tid == 0) {
        unsigned v = atomicAdd(&g_done, 1u);
        s_last = (v == GRID_B - 1) ? 1u : 0u;
    }
    __syncthreads();
    if (s_last) {
        __threadfence();
        float a = 0.0f, b = 0.0f;
        for (int i = tid; i < GRID_B; i += 256) a += g_inter_part[i];
        for (int i = tid; i < GNUM; i += 256) b += g_intra_part[i];
        #pragma unroll
        for (int o = 16; o > 0; o >>= 1) {
            a += __shfl_down_sync(0xffffffffu, a, o);
            b += __shfl_down_sync(0xffffffffu, b, o);
        }
        __shared__ float fa[8], fb[8];
        if (lane == 0) { fa[wid] = a; fb[wid] = b; }
        __syncthreads();
        if (tid == 0) {
            float A = 0.0f, B = 0.0f;
            #pragma unroll
            for (int w = 0; w < 8; w++) { A += fa[w]; B += fb[w]; }
            out[0] = A / 33550336.0f;              // G*(G-1)/2
            out[1] = B / (float)(GNUM * PNUM);
            g_done = 0;                            // reset for next replay
            g_sqmin_bits = 0x7F7FFFFFu;
        }
    }
}

extern "C" void kernel_launch(void* const* d_in, const int* in_sizes, int n_in,
                              void* d_out, int out_size) {
    const float* fea = (const float*)d_in[0];
    float* out = (float*)d_out;

    center_intra_kernel<<<GNUM, 512>>>(fea);

    const int smem_bytes = 3 * TILEB;   // 55296
    cudaFuncSetAttribute(gram_finalize_kernel,
                         cudaFuncAttributeMaxDynamicSharedMemorySize, smem_bytes);
    gram_finalize_kernel<<<GRID_B, 256, smem_bytes>>>(out);
}

// round 13
// speedup vs baseline: 1.0321x; 1.0321x over previous
#include <cuda_runtime.h>
#include <cuda_bf16.h>
#include <cuda_fp16.h>
#include <cuda_fp8.h>
#include <cstdint>

// Problem constants (fixed shape: path_fea [131072, 64, 1, 1, 2] fp32)
#define GNUM 8192        // groups = B / 16
#define PNUM 16          // samples per group
#define DNUM 128         // feature dim
#define NTILE 64         // GNUM / 128
#define NTILES_TRI 2080  // 64*65/2 triangular 128x128 tiles
#define GRID_B 444       // persistent CTAs (148 SMs * 3)
#define TROW 144         // smem tile row stride in bytes (128 fp8 + 16 pad)
#define TILEB (128 * TROW)

// -------- device scratch (no allocs allowed) --------
__device__ uint8_t g_centerF8[GNUM * DNUM];   // e4m3 centers (k-major, 128B/row)
__device__ float g_sq[GNUM];                  // fp32 ||c||^2
__device__ float g_intra_part[GNUM];
__device__ float g_inter_part[GRID_B];
__device__ unsigned int g_sqmin_bits = 0x7F7FFFFFu;  // FLT_MAX bits; self-resetting
__device__ unsigned int g_done = 0;                  // self-resetting

// ===================== helpers =====================
__device__ __forceinline__ uint32_t smem_u32(const void* p) {
    uint32_t a;
    asm("{ .reg .u64 t; cvta.to.shared.u64 t, %1; cvt.u32.u64 %0, t; }"
        : "=r"(a) : "l"(p));
    return a;
}
__device__ __forceinline__ void cp16(uint32_t dst, const void* src) {
    asm volatile("cp.async.cg.shared.global [%0], [%1], 16;"
                 :: "r"(dst), "l"(src) : "memory");
}
__device__ __forceinline__ void cp_commit() {
    asm volatile("cp.async.commit_group;" ::: "memory");
}
__device__ __forceinline__ void cp_wait0() {
    asm volatile("cp.async.wait_group 0;" ::: "memory");
}
__device__ __forceinline__ void ldm_x4_raw(uint32_t (&r)[4], uint32_t addr) {
    asm volatile("ldmatrix.sync.aligned.m8n8.x4.shared.b16 {%0,%1,%2,%3}, [%4];"
        : "=r"(r[0]), "=r"(r[1]), "=r"(r[2]), "=r"(r[3]) : "r"(addr));
}
// FP8 e4m3 MMA with f16 accumulators
__device__ __forceinline__ void mma_fp8_h(uint32_t (&d)[2], const uint32_t (&a)[4],
                                          uint32_t b0, uint32_t b1) {
    asm volatile(
        "mma.sync.aligned.m16n8k32.row.col.f16.e4m3.e4m3.f16 "
        "{%0,%1}, {%2,%3,%4,%5}, {%6,%7}, {%0,%1};"
        : "+r"(d[0]), "+r"(d[1])
        : "r"(a[0]), "r"(a[1]), "r"(a[2]), "r"(a[3]), "r"(b0), "r"(b1));
}

// ============================================================
// Kernel A: per-group center + ||c||^2 + intra hinge (memory-bound,
// wide grid to saturate HBM) + global-min(||c||^2) via atomicMin
// ============================================================
__global__ void __launch_bounds__(512) center_intra_kernel(const float* __restrict__ fea) {
    __shared__ float sf[PNUM * DNUM];
    __shared__ float sc[DNUM];
    __shared__ float s_red[4];
    __shared__ float s_h[PNUM];

    const int g = blockIdx.x;
    const int tid = threadIdx.x;

    const float4* base4 = (const float4*)(fea + (size_t)g * (PNUM * DNUM));
    ((float4*)sf)[tid] = base4[tid];
    __syncthreads();

    float c = 0.0f;
    if (tid < DNUM) {
        #pragma unroll
        for (int s = 0; s < PNUM; s++) c += sf[s * DNUM + tid];
        c *= (1.0f / PNUM);
        sc[tid] = c;
        g_centerF8[(size_t)g * DNUM + tid] =
            (uint8_t)__nv_cvt_float_to_fp8(c, __NV_SATFINITE, __NV_E4M3);
    }
    float cs = (tid < DNUM) ? c * c : 0.0f;
    #pragma unroll
    for (int o = 16; o > 0; o >>= 1) cs += __shfl_down_sync(0xffffffffu, cs, o);
    if (tid < DNUM && (tid & 31) == 0) s_red[tid >> 5] = cs;
    __syncthreads();
    if (tid == 0) {
        float sq = s_red[0] + s_red[1] + s_red[2] + s_red[3];
        g_sq[g] = sq;
        atomicMin(&g_sqmin_bits, __float_as_uint(sq));  // sq >= 0: bit order = float order
    }

    const int w = tid >> 5, l = tid & 31;
    float acc = 0.0f;
    #pragma unroll
    for (int q = 0; q < 4; q++) {
        int dd = l + 32 * q;
        float df = sf[w * DNUM + dd] - sc[dd];
        acc += df * df;
    }
    #pragma unroll
    for (int o = 16; o > 0; o >>= 1) acc += __shfl_down_sync(0xffffffffu, acc, o);
    if (l == 0) {
        float d = fmaxf(sqrtf(acc) - 0.1f, 0.0f);
        s_h[w] = d * d;
    }
    __syncthreads();
    if (tid == 0) {
        float t = 0.0f;
        #pragma unroll
        for (int s = 0; s < PNUM; s++) t += s_h[s];
        g_intra_part[g] = t;
    }
}

// ============================================================
// Kernel B: persistent FP8 QMMA SYRK (128x128 tiles, f16 accum),
// A+B double-buffered (4 x 18KB = 72KB, 3 CTAs/SM), raw-address LDSM,
// max-screened hinge epilogue, fused finalize (last CTA).
// ============================================================
__global__ void __launch_bounds__(256, 3) gram_finalize_kernel(float* __restrict__ out) {
    extern __shared__ uint8_t sm[];
    uint8_t* bufA[2] = { sm, sm + TILEB };
    uint8_t* bufB[2] = { sm + 2 * TILEB, sm + 3 * TILEB };

    __shared__ float s_red[8];
    __shared__ unsigned s_last;

    const int tid = threadIdx.x;
    const int wid = tid >> 5, lane = tid & 31;

    const int t0 = (int)(((long long)blockIdx.x * NTILES_TRI) / GRID_B);
    const int t1 = (int)(((long long)(blockIdx.x + 1) * NTILES_TRI) / GRID_B);

    int ti = 0, rowoff = 0;
    while (t0 >= rowoff + (NTILE - ti)) { rowoff += NTILE - ti; ti++; }
    int tj = ti + (t0 - rowoff);

    const uint8_t* gcb = g_centerF8;
    auto load_tile = [&](uint8_t* dst, int g0) {
        #pragma unroll
        for (int i = 0; i < 4; i++) {
            int u = tid + 256 * i;
            int r = u >> 3, c16 = (u & 7) * 16;
            cp16(smem_u32(dst + r * TROW + c16),
                 gcb + (size_t)(g0 + r) * 128 + c16);
        }
    };

    // prologue loads
    load_tile(bufA[0], ti * 128);
    load_tile(bufB[0], tj * 128);
    cp_commit();

    const float screen = __uint_as_float(g_sqmin_bits) - 0.5f;

    const int wm = wid & 1;
    const int wn = wid >> 1;
    const int lrow = lane & 15;
    const int lcolB = ((lane >> 4) << 3) * 2;
    const int r_l = lane >> 2;
    const int c_l = 2 * (lane & 3);

    // precomputed per-warp raw smem base addresses (loop-constant)
    const uint32_t aBase[2] = {
        smem_u32(bufA[0]) + (64 * wm + lrow) * TROW + lcolB,
        smem_u32(bufA[1]) + (64 * wm + lrow) * TROW + lcolB };
    const uint32_t bBase[2] = {
        smem_u32(bufB[0]) + (32 * wn + lrow) * TROW + lcolB,
        smem_u32(bufB[1]) + (32 * wn + lrow) * TROW + lcolB };

    int aCur = 0, bCur = 0;
    float lsum = 0.0f;

    for (int t = t0; t < t1; t++) {
        const int i0 = ti * 128, j0 = tj * 128;
        cp_wait0();
        __syncthreads();

        int nti = ti, ntj = tj + 1;
        if (ntj == NTILE) { nti = ti + 1; ntj = nti; }
        const bool havenext = (t + 1 < t1);
        const bool newrow = (nti != ti);
        if (havenext) {
            if (newrow) load_tile(bufA[aCur ^ 1], nti * 128);
            load_tile(bufB[bCur ^ 1], ntj * 128);
            cp_commit();
        }

        // ---- compute 128x128 tile: 4 k-steps of k32 (raw-address LDSM) ----
        const uint32_t aB = aBase[aCur];
        const uint32_t bB = bBase[bCur];
        uint32_t acc[4][4][2];
        #pragma unroll
        for (int mt = 0; mt < 4; mt++)
            #pragma unroll
            for (int nt = 0; nt < 4; nt++) { acc[mt][nt][0] = 0u; acc[mt][nt][1] = 0u; }

        #pragma unroll
        for (int ks = 0; ks < 4; ks++) {
            const int kb = ks * 32;
            uint32_t a[4][4];
            #pragma unroll
            for (int mt = 0; mt < 4; mt++)
                ldm_x4_raw(a[mt], aB + mt * (16 * TROW) + kb);
            uint32_t b0r[4], b1r[4];
            ldm_x4_raw(b0r, bB + kb);
            ldm_x4_raw(b1r, bB + 16 * TROW + kb);

            #pragma unroll
            for (int mt = 0; mt < 4; mt++) {
                mma_fp8_h(acc[mt][0], a[mt], b0r[0], b0r[2]);
                mma_fp8_h(acc[mt][1], a[mt], b0r[1], b0r[3]);
                mma_fp8_h(acc[mt][2], a[mt], b1r[0], b1r[2]);
                mma_fp8_h(acc[mt][3], a[mt], b1r[1], b1r[3]);
            }
        }

        // ---- epilogue: packed-max screen, exact path only if needed ----
        const bool diag = (ti == tj);
        __half2 m2 = __float2half2_rn(-60000.0f);
        #pragma unroll
        for (int mt = 0; mt < 4; mt++)
            #pragma unroll
            for (int nt = 0; nt < 4; nt++) {
                m2 = __hmax2(m2, *(const __half2*)&acc[mt][nt][0]);
                m2 = __hmax2(m2, *(const __half2*)&acc[mt][nt][1]);
            }
        float maxg = fmaxf(__low2float(m2), __high2float(m2));

        if (diag || maxg > screen) {
            // exact (diagonal tiles / vanishingly rare screen failures)
            #pragma unroll 1
            for (int mt = 0; mt < 4; mt++) {
                const int li0 = 64 * wm + 16 * mt + r_l;
                const float qa0 = __ldg(&g_sq[i0 + li0]);
                const float qa1 = __ldg(&g_sq[i0 + li0 + 8]);
                #pragma unroll 1
                for (int nt = 0; nt < 4; nt++) {
                    const int lj0 = 32 * wn + 8 * nt + c_l;
                    const float qb0 = __ldg(&g_sq[j0 + lj0]);
                    const float qb1 = __ldg(&g_sq[j0 + lj0 + 1]);
                    float2 v0 = __half22float2(*(const __half2*)&acc[mt][nt][0]);
                    float2 v1 = __half22float2(*(const __half2*)&acc[mt][nt][1]);
                    const float gv[4]  = { v0.x, v0.y, v1.x, v1.y };
                    const float qav[4] = { qa0, qa0, qa1, qa1 };
                    const float qbv[4] = { qb0, qb1, qb0, qb1 };
                    const int liv[4] = { li0, li0, li0 + 8, li0 + 8 };
                    const int ljv[4] = { lj0, lj0 + 1, lj0, lj0 + 1 };
                    #pragma unroll
                    for (int e = 0; e < 4; e++) {
                        bool ok = !diag || (liv[e] < ljv[e]);
                        float d2 = qav[e] + qbv[e] - 2.0f * gv[e];
                        if (ok && d2 < 1.0f) {
                            float d = sqrtf(fmaxf(d2, 0.0f));
                            float h = 1.0f - d;
                            lsum += h * h;
                        }
                    }
                }
            }
        }

        if (havenext) {
            if (newrow) aCur ^= 1;
            bCur ^= 1;
            ti = nti; tj = ntj;
        }
    }

    // per-CTA inter reduction
    #pragma unroll
    for (int o = 16; o > 0; o >>= 1) lsum += __shfl_down_sync(0xffffffffu, lsum, o);
    __syncthreads();
    if (lane == 0) s_red[wid] = lsum;
    __syncthreads();
    if (tid == 0) {
        float tsum = 0.0f;
        #pragma unroll
        for (int w = 0; w < 8; w++) tsum += s_red[w];
        g_inter_part[blockIdx.x] = tsum;
    }

    // last-CTA-done finalize
    __threadfence();
    __syncthreads();
    if (tid == 0) {
        unsigned v = atomicAdd(&g_done, 1u);
        s_last = (v == GRID_B - 1) ? 1u : 0u;
    }
    __syncthreads();
    if (s_last) {
        __threadfence();
        float a = 0.0f, b = 0.0f;
        for (int i = tid; i < GRID_B; i += 256) a += g_inter_part[i];
        for (int i = tid; i < GNUM; i += 256) b += g_intra_part[i];
        #pragma unroll
        for (int o = 16; o > 0; o >>= 1) {
            a += __shfl_down_sync(0xffffffffu, a, o);
            b += __shfl_down_sync(0xffffffffu, b, o);
        }
        __shared__ float fa[8], fb[8];
        if (lane == 0) { fa[wid] = a; fb[wid] = b; }
        __syncthreads();
        if (tid == 0) {
            float A = 0.0f, B = 0.0f;
            #pragma unroll
            for (int w = 0; w < 8; w++) { A += fa[w]; B += fb[w]; }
            out[0] = A / 33550336.0f;              // G*(G-1)/2
            out[1] = B / (float)(GNUM * PNUM);
            g_done = 0;                            // reset for next replay
            g_sqmin_bits = 0x7F7FFFFFu;
        }
    }
}

extern "C" void kernel_launch(void* const* d_in, const int* in_sizes, int n_in,
                              void* d_out, int out_size) {
    const float* fea = (const float*)d_in[0];
    float* out = (float*)d_out;

    center_intra_kernel<<<GNUM, 512>>>(fea);

    const int smem_bytes = 4 * TILEB;   // 73728
    cudaFuncSetAttribute(gram_finalize_kernel,
                         cudaFuncAttributeMaxDynamicSharedMemorySize, smem_bytes);
    gram_finalize_kernel<<<GRID_B, 256, smem_bytes>>>(out);
}

// round 14
// speedup vs baseline: 1.1579x; 1.1219x over previous
#include <cuda_runtime.h>
#include <cuda_bf16.h>
#include <cuda_fp16.h>
#include <cuda_fp8.h>
#include <cstdint>

// Problem constants (fixed shape: path_fea [131072, 64, 1, 1, 2] fp32)
#define GNUM 8192        // groups = B / 16
#define PNUM 16          // samples per group
#define DNUM 128         // feature dim
#define KSUB 64          // screening subset: first 64 dims (d^2 >= d^2_sub)
#define NTILE 64         // GNUM / 128
#define NTILES_TRI 2080  // 64*65/2 triangular 128x128 tiles
#define GRID_B 444       // persistent CTAs (148 SMs * 3)
#define TROW 80          // smem tile row stride in bytes (64 fp8 + 16 pad)
#define TILEB (128 * TROW)   // 10240 B per tile

// -------- device scratch (no allocs allowed) --------
__device__ uint8_t g_centerF8[GNUM * KSUB];   // e4m3 centers, first 64 dims
__device__ __half  g_centerHf[GNUM * DNUM];   // fp16 centers (exact fallback)
__device__ __half  g_q64h[GNUM];              // partial ||c||^2 over first 64 dims
__device__ float g_intra_part[GNUM];
__device__ float g_inter_part[GRID_B];
__device__ unsigned int g_done = 0;           // self-resetting

// ===================== helpers =====================
__device__ __forceinline__ uint32_t smem_u32(const void* p) {
    uint32_t a;
    asm("{ .reg .u64 t; cvta.to.shared.u64 t, %1; cvt.u32.u64 %0, t; }"
        : "=r"(a) : "l"(p));
    return a;
}
__device__ __forceinline__ void cp16(uint32_t dst, const void* src) {
    asm volatile("cp.async.cg.shared.global [%0], [%1], 16;"
                 :: "r"(dst), "l"(src) : "memory");
}
__device__ __forceinline__ void cp_commit() {
    asm volatile("cp.async.commit_group;" ::: "memory");
}
__device__ __forceinline__ void cp_wait0() {
    asm volatile("cp.async.wait_group 0;" ::: "memory");
}
__device__ __forceinline__ void ldm_x4_raw(uint32_t (&r)[4], uint32_t addr) {
    asm volatile("ldmatrix.sync.aligned.m8n8.x4.shared.b16 {%0,%1,%2,%3}, [%4];"
        : "=r"(r[0]), "=r"(r[1]), "=r"(r[2]), "=r"(r[3]) : "r"(addr));
}
// FP8 e4m3 MMA with f16 accumulators
__device__ __forceinline__ void mma_fp8_h(uint32_t (&d)[2], const uint32_t (&a)[4],
                                          uint32_t b0, uint32_t b1) {
    asm volatile(
        "mma.sync.aligned.m16n8k32.row.col.f16.e4m3.e4m3.f16 "
        "{%0,%1}, {%2,%3,%4,%5}, {%6,%7}, {%0,%1};"
        : "+r"(d[0]), "+r"(d[1])
        : "r"(a[0]), "r"(a[1]), "r"(a[2]), "r"(a[3]), "r"(b0), "r"(b1));
}

// ============================================================
// Kernel A: per-group center + intra hinge + fp8(first 64 dims) +
// fp16 centers + q64 table (memory-bound, wide grid)
// ============================================================
__global__ void __launch_bounds__(512) center_intra_kernel(const float* __restrict__ fea) {
    __shared__ float sf[PNUM * DNUM];
    __shared__ float sc[DNUM];
    __shared__ float s_red[4];
    __shared__ float s_h[PNUM];

    const int g = blockIdx.x;
    const int tid = threadIdx.x;

    const float4* base4 = (const float4*)(fea + (size_t)g * (PNUM * DNUM));
    ((float4*)sf)[tid] = base4[tid];
    __syncthreads();

    float c = 0.0f;
    if (tid < DNUM) {
        #pragma unroll
        for (int s = 0; s < PNUM; s++) c += sf[s * DNUM + tid];
        c *= (1.0f / PNUM);
        sc[tid] = c;
        g_centerHf[(size_t)g * DNUM + tid] = __float2half(c);
        if (tid < KSUB)
            g_centerF8[(size_t)g * KSUB + tid] =
                (uint8_t)__nv_cvt_float_to_fp8(c, __NV_SATFINITE, __NV_E4M3);
    }
    float cs = (tid < DNUM) ? c * c : 0.0f;
    #pragma unroll
    for (int o = 16; o > 0; o >>= 1) cs += __shfl_down_sync(0xffffffffu, cs, o);
    if (tid < DNUM && (tid & 31) == 0) s_red[tid >> 5] = cs;
    __syncthreads();
    if (tid == 0)
        g_q64h[g] = __float2half(s_red[0] + s_red[1]);   // dims 0..63

    const int w = tid >> 5, l = tid & 31;
    float acc = 0.0f;
    #pragma unroll
    for (int q = 0; q < 4; q++) {
        int dd = l + 32 * q;
        float df = sf[w * DNUM + dd] - sc[dd];
        acc += df * df;
    }
    #pragma unroll
    for (int o = 16; o > 0; o >>= 1) acc += __shfl_down_sync(0xffffffffu, acc, o);
    if (l == 0) {
        float d = fmaxf(sqrtf(acc) - 0.1f, 0.0f);
        s_h[w] = d * d;
    }
    __syncthreads();
    if (tid == 0) {
        float t = 0.0f;
        #pragma unroll
        for (int s = 0; s < PNUM; s++) t += s_h[s];
        g_intra_part[g] = t;
    }
}

// ============================================================
// Kernel B: persistent FP8 half-Gram SYRK (K=64, 128x128 tiles, f16 acc),
// A+B double-buffered (4 x 10KB smem), per-element half2 screen at d2>=2,
// exact fp16 fallback (handles diagonal + rare screen failures),
// fused finalize (last CTA).
// ============================================================
__global__ void __launch_bounds__(256, 3) gram_finalize_kernel(float* __restrict__ out) {
    extern __shared__ uint8_t sm[];
    uint8_t* bufA[2] = { sm, sm + TILEB };
    uint8_t* bufB[2] = { sm + 2 * TILEB, sm + 3 * TILEB };

    __shared__ float s_red[8];
    __shared__ unsigned s_last;

    const int tid = threadIdx.x;
    const int wid = tid >> 5, lane = tid & 31;

    const int t0 = (int)(((long long)blockIdx.x * NTILES_TRI) / GRID_B);
    const int t1 = (int)(((long long)(blockIdx.x + 1) * NTILES_TRI) / GRID_B);

    int ti = 0, rowoff = 0;
    while (t0 >= rowoff + (NTILE - ti)) { rowoff += NTILE - ti; ti++; }
    int tj = ti + (t0 - rowoff);

    const uint8_t* gcb = g_centerF8;
    auto load_tile = [&](uint8_t* dst, int g0) {
        #pragma unroll
        for (int i = 0; i < 2; i++) {
            int u = tid + 256 * i;
            int r = u >> 2, c16 = (u & 3) * 16;
            cp16(smem_u32(dst + r * TROW + c16),
                 gcb + (size_t)(g0 + r) * KSUB + c16);
        }
    };

    // prologue loads
    load_tile(bufA[0], ti * 128);
    load_tile(bufB[0], tj * 128);
    cp_commit();

    const int wm = wid & 1;
    const int wn = wid >> 1;
    const int lrow = lane & 15;
    const int lcolB = (lane >> 4) * 16;
    const int r_l = lane >> 2;
    const int c_l = 2 * (lane & 3);

    // precomputed per-warp raw smem base addresses (loop-constant)
    const uint32_t aBase[2] = {
        smem_u32(bufA[0]) + (64 * wm + lrow) * TROW + lcolB,
        smem_u32(bufA[1]) + (64 * wm + lrow) * TROW + lcolB };
    const uint32_t bBase[2] = {
        smem_u32(bufB[0]) + (32 * wn + lrow) * TROW + lcolB,
        smem_u32(bufB[1]) + (32 * wn + lrow) * TROW + lcolB };

    const __half2 neg2 = __float2half2_rn(-2.0f);

    int aCur = 0, bCur = 0;
    float lsum = 0.0f;

    for (int t = t0; t < t1; t++) {
        const int i0 = ti * 128, j0 = tj * 128;
        cp_wait0();
        __syncthreads();

        int nti = ti, ntj = tj + 1;
        if (ntj == NTILE) { nti = ti + 1; ntj = nti; }
        const bool havenext = (t + 1 < t1);
        const bool newrow = (nti != ti);
        if (havenext) {
            if (newrow) load_tile(bufA[aCur ^ 1], nti * 128);
            load_tile(bufB[bCur ^ 1], ntj * 128);
            cp_commit();
        }

        // ---- compute 128x128 half-Gram: 2 k-steps of k32 ----
        const uint32_t aB = aBase[aCur];
        const uint32_t bB = bBase[bCur];
        uint32_t acc[4][4][2];
        #pragma unroll
        for (int mt = 0; mt < 4; mt++)
            #pragma unroll
            for (int nt = 0; nt < 4; nt++) { acc[mt][nt][0] = 0u; acc[mt][nt][1] = 0u; }

        #pragma unroll
        for (int ks = 0; ks < 2; ks++) {
            const int kb = ks * 32;
            uint32_t a[4][4];
            #pragma unroll
            for (int mt = 0; mt < 4; mt++)
                ldm_x4_raw(a[mt], aB + mt * (16 * TROW) + kb);
            uint32_t b0r[4], b1r[4];
            ldm_x4_raw(b0r, bB + kb);
            ldm_x4_raw(b1r, bB + 16 * TROW + kb);

            #pragma unroll
            for (int mt = 0; mt < 4; mt++) {
                mma_fp8_h(acc[mt][0], a[mt], b0r[0], b0r[2]);
                mma_fp8_h(acc[mt][1], a[mt], b0r[1], b0r[3]);
                mma_fp8_h(acc[mt][2], a[mt], b1r[0], b1r[2]);
                mma_fp8_h(acc[mt][3], a[mt], b1r[1], b1r[3]);
            }
        }

        // ---- epilogue: per-element screen  d2_64 = qa+qb-2g >= 2.0 ----
        const bool diag = (ti == tj);

        __half2 qa2[8];
        #pragma unroll
        for (int mt = 0; mt < 4; mt++) {
            const int li0 = i0 + 64 * wm + 16 * mt + r_l;
            qa2[2 * mt]     = __half2half2(__ldg(&g_q64h[li0]));
            qa2[2 * mt + 1] = __half2half2(__ldg(&g_q64h[li0 + 8]));
        }
        __half2 qb2[4];
        #pragma unroll
        for (int nt = 0; nt < 4; nt++)
            qb2[nt] = __ldg((const __half2*)&g_q64h[j0 + 32 * wn + 8 * nt + c_l]);

        __half2 mn2 = __float2half2_rn(60000.0f);
        #pragma unroll
        for (int mt = 0; mt < 4; mt++) {
            #pragma unroll
            for (int nt = 0; nt < 4; nt++) {
                __half2 s0 = __hadd2(qa2[2 * mt], qb2[nt]);
                __half2 s1 = __hadd2(qa2[2 * mt + 1], qb2[nt]);
                mn2 = __hmin2(mn2, __hfma2(*(const __half2*)&acc[mt][nt][0], neg2, s0));
                mn2 = __hmin2(mn2, __hfma2(*(const __half2*)&acc[mt][nt][1], neg2, s1));
            }
        }
        float fmn = fminf(__low2float(mn2), __high2float(mn2));

        if (diag || fmn < 2.0f) {
            // slow path: per-element exact check (diagonal / rare failures)
            #pragma unroll 1
            for (int mt = 0; mt < 4; mt++) {
                #pragma unroll 1
                for (int nt = 0; nt < 4; nt++) {
                    #pragma unroll 1
                    for (int rg = 0; rg < 2; rg++) {
                        float2 g2 = __half22float2(*(const __half2*)&acc[mt][nt][rg]);
                        float qaf = __low2float(qa2[2 * mt + rg]);
                        float2 qbf = __half22float2(qb2[nt]);
                        const int gi = i0 + 64 * wm + 16 * mt + r_l + 8 * rg;
                        #pragma unroll 1
                        for (int e = 0; e < 2; e++) {
                            const int gj = j0 + 32 * wn + 8 * nt + c_l + e;
                            float gval = e ? g2.y : g2.x;
                            float v = qaf + (e ? qbf.y : qbf.x) - 2.0f * gval;
                            if (v < 2.0f && gi < gj) {
                                // exact full-dim distance from fp16 centers
                                const __half2* ci = (const __half2*)&g_centerHf[(size_t)gi * DNUM];
                                const __half2* cj = (const __half2*)&g_centerHf[(size_t)gj * DNUM];
                                float d2 = 0.0f;
                                #pragma unroll 1
                                for (int k = 0; k < DNUM / 2; k++) {
                                    float2 av = __half22float2(ci[k]);
                                    float2 bv = __half22float2(cj[k]);
                                    float dx = av.x - bv.x, dy = av.y - bv.y;
                                    d2 += dx * dx + dy * dy;
                                }
                                if (d2 < 1.0f) {
                                    float d = sqrtf(fmaxf(d2, 0.0f));
                                    float h = 1.0f - d;
                                    lsum += h * h;
                                }
                            }
                        }
                    }
                }
            }
        }

        if (havenext) {
            if (newrow) aCur ^= 1;
            bCur ^= 1;
            ti = nti; tj = ntj;
        }
    }

    // per-CTA inter reduction
    #pragma unroll
    for (int o = 16; o > 0; o >>= 1) lsum += __shfl_down_sync(0xffffffffu, lsum, o);
    __syncthreads();
    if (lane == 0) s_red[wid] = lsum;
    __syncthreads();
    if (tid == 0) {
        float tsum = 0.0f;
        #pragma unroll
        for (int w = 0; w < 8; w++) tsum += s_red[w];
        g_inter_part[blockIdx.x] = tsum;
    }

    // last-CTA-done finalize
    __threadfence();
    __syncthreads();
    if (tid == 0) {
        unsigned v = atomicAdd(&g_done, 1u);
        s_last = (v == GRID_B - 1) ? 1u : 0u;
    }
    __syncthreads();
    if (s_last) {
        __threadfence();
        float a = 0.0f, b = 0.0f;
        for (int i = tid; i < GRID_B; i += 256) a += g_inter_part[i];
        for (int i = tid; i < GNUM; i += 256) b += g_intra_part[i];
        #pragma unroll
        for (int o = 16; o > 0; o >>= 1) {
            a += __shfl_down_sync(0xffffffffu, a, o);
            b += __shfl_down_sync(0xffffffffu, b, o);
        }
        __shared__ float fa[8], fb[8];
        if (lane == 0) { fa[wid] = a; fb[wid] = b; }
        __syncthreads();
        if (tid == 0) {
            float A = 0.0f, B = 0.0f;
            #pragma unroll
            for (int w = 0; w < 8; w++) { A += fa[w]; B += fb[w]; }
            out[0] = A / 33550336.0f;              // G*(G-1)/2
            out[1] = B / (float)(GNUM * PNUM);
            g_done = 0;                            // reset for next replay
        }
    }
}

extern "C" void kernel_launch(void* const* d_in, const int* in_sizes, int n_in,
                              void* d_out, int out_size) {
    const float* fea = (const float*)d_in[0];
    float* out = (float*)d_out;

    center_intra_kernel<<<GNUM, 512>>>(fea);

    const int smem_bytes = 4 * TILEB;   // 40960
    cudaFuncSetAttribute(gram_finalize_kernel,
                         cudaFuncAttributeMaxDynamicSharedMemorySize, smem_bytes);
    gram_finalize_kernel<<<GRID_B, 256, smem_bytes>>>(out);
}